// round 4
// baseline (speedup 1.0000x reference)
#include <cuda_runtime.h>
#include <cstdint>

#define Nn 2048
#define Dd 64
#define Vv 2048
#define TB 128                      // pair tile dim
#define NT (Nn / TB)                // 16 tiles per dim
#define NTILES (NT * (NT + 1) / 2)  // 136 triangle tiles
#define PADK 33                     // float2 row stride (pad) -> conflict-free
#define MAXB 148                    // k_max blocks

// Scratch (no allocations -> __device__ globals). All slots are fully
// overwritten every call (deterministic, no init kernel needed).
__device__ float g_table[(size_t)Vv * Vv];   // fused metric table, 16MB
__device__ float g_part[MAXB];               // per-block maxes
__device__ float g_psum[NTILES], g_pcnt[NTILES];

// ---------------------------------------------------------------------------
__device__ __forceinline__ unsigned long long f2add(unsigned long long a,
                                                    unsigned long long b) {
    unsigned long long r;
    asm("add.rn.f32x2 %0, %1, %2;" : "=l"(r) : "l"(a), "l"(b));
    return r;
}

__device__ __forceinline__ void cpa4(uint32_t dst, const float* src) {
    asm volatile("cp.async.ca.shared.global [%0], [%1], 4;" :: "r"(dst), "l"(src));
}

__device__ __forceinline__ uint32_t s2u(const void* p) {
    return (uint32_t)__cvta_generic_to_shared(p);
}

// ---------------------------------------------------------------------------
// per-block max over map_dist -> g_part[bid] (plain store, no init needed)
__global__ __launch_bounds__(1024) void k_max(const float4* __restrict__ m) {
    __shared__ float sred[32];
    float v = 0.0f;
    for (int i = blockIdx.x * 1024 + threadIdx.x; i < (Vv * Vv / 4);
         i += MAXB * 1024) {
        float4 x = m[i];
        v = fmaxf(fmaxf(v, fmaxf(x.x, x.y)), fmaxf(x.z, x.w));
    }
#pragma unroll
    for (int o = 16; o; o >>= 1) v = fmaxf(v, __shfl_xor_sync(0xffffffffu, v, o));
    int lane = threadIdx.x & 31, w = threadIdx.x >> 5;
    if (lane == 0) sred[w] = v;
    __syncthreads();
    if (w == 0) {
        v = sred[lane];
#pragma unroll
        for (int o = 16; o; o >>= 1) v = fmaxf(v, __shfl_xor_sync(0xffffffffu, v, o));
        if (lane == 0) g_part[blockIdx.x] = v;
    }
}

// fused table: M = 0.5*tree + (0.5/largest)*map ; each block reduces g_part
__global__ __launch_bounds__(1024) void k_table(const float4* __restrict__ tree,
                                                const float4* __restrict__ mapd) {
    __shared__ float ssc;
    if (threadIdx.x < 32) {
        float v = 0.0f;
        for (int k = threadIdx.x; k < MAXB; k += 32) v = fmaxf(v, g_part[k]);
#pragma unroll
        for (int o = 16; o; o >>= 1) v = fmaxf(v, __shfl_xor_sync(0xffffffffu, v, o));
        if (threadIdx.x == 0) ssc = 0.5f / v;
    }
    __syncthreads();
    float sc = ssc;
    int i = blockIdx.x * 1024 + threadIdx.x;  // grid covers V*V/4
    float4 t = tree[i], m = mapd[i];
    float4 o;
    o.x = 0.5f * t.x + sc * m.x;
    o.y = 0.5f * t.y + sc * m.y;
    o.z = 0.5f * t.z + sc * m.z;
    o.w = 0.5f * t.w + sc * m.w;
    ((float4*)g_table)[i] = o;
}

// ---------------------------------------------------------------------------
extern __shared__ unsigned long long smem_raw[];

// 1024 threads: thread (tx=tid&31, ty=tid>>5) owns rows ty+32r (r<4),
// cols tx+32c (c<4). a-loads warp-uniform (broadcast), b-loads stride PADK
// conflict-free per half-warp phase. Metric gathers issued via cp.async at
// loop start; latency hidden behind the whole mainloop.
__global__ __launch_bounds__(1024, 1) void k_main(const int* __restrict__ ids,
                                                  const float2* __restrict__ emb) {
    int tid = threadIdx.x;
    int t = blockIdx.x, bi = 0;
    while (t >= NT - bi) { t -= NT - bi; bi++; }
    int bj = bi + t;
    int ibase = bi * TB, jbase = bj * TB;
    bool offdiag = (bi != bj);

    unsigned long long* sA = smem_raw;               // [128][PADK] f32x2
    unsigned long long* sB = smem_raw + TB * PADK;   // negated j-tile
    int* sIdI = (int*)(smem_raw + 2 * TB * PADK);
    int* sIdJ = sIdI + TB;
    float* sM = (float*)(sIdJ + TB);                 // [16][1024] gathered metric

    int tx = tid & 31, ty = tid >> 5;

    // ids first (cp.async gather addresses need them)
    if (tid < TB) {
        sIdI[tid] = ids[ibase + tid];
        sIdJ[tid] = ids[jbase + tid];
    }
    __syncthreads();

    // issue 16 metric gathers (plane-major: sM[p*1024 + tid])
    {
        uint32_t dstb = s2u(sM) + tid * 4u;
#pragma unroll
        for (int r = 0; r < 4; r++) {
            const float* trow = g_table + (size_t)sIdI[ty + 32 * r] * Vv;
#pragma unroll
            for (int c = 0; c < 4; c++) {
                cpa4(dstb + (r * 4 + c) * 4096u, trow + sIdJ[tx + 32 * c]);
            }
        }
        asm volatile("cp.async.commit_group;");
    }

    // embedding tiles (coalesced; B negated so diff = packed add)
    for (int x = tid; x < TB * 32; x += 1024) {
        int row = x >> 5, k2 = x & 31;
        float2 a = emb[(ibase + row) * 32 + k2];
        float2 b = emb[(jbase + row) * 32 + k2];
        ((float2*)sA)[row * PADK + k2] = a;
        b.x = -b.x; b.y = -b.y;
        ((float2*)sB)[row * PADK + k2] = b;
    }
    __syncthreads();

    unsigned long long acc[4][4];
#pragma unroll
    for (int r = 0; r < 4; r++)
#pragma unroll
        for (int c = 0; c < 4; c++) acc[r][c] = 0ull;

    const unsigned long long ABSM = 0x7FFFFFFF7FFFFFFFull;
    const unsigned long long* sArow = sA + ty * PADK;
    const unsigned long long* sBrow = sB + tx * PADK;

#pragma unroll 4
    for (int k2 = 0; k2 < 32; k2++) {
        unsigned long long a2[4], b2[4];
#pragma unroll
        for (int r = 0; r < 4; r++) a2[r] = sArow[(32 * r) * PADK + k2];
#pragma unroll
        for (int c = 0; c < 4; c++) b2[c] = sBrow[(32 * c) * PADK + k2];
#pragma unroll
        for (int r = 0; r < 4; r++) {
#pragma unroll
            for (int c = 0; c < 4; c++) {
                unsigned long long d = f2add(a2[r], b2[c]);  // a - b (packed)
                d &= ABSM;                                   // |.| both halves
                acc[r][c] = f2add(acc[r][c], d);
            }
        }
    }

    // gathers landed long ago; drain the async group
    asm volatile("cp.async.wait_group 0;" ::: "memory");
    __syncthreads();

    // epilogue: pure math
    float loss = 0.0f, cnt = 0.0f;
    const float inv64 = 1.0f / 64.0f;
#pragma unroll
    for (int r = 0; r < 4; r++) {
        int ir = ty + 32 * r;
        int idi = sIdI[ir];
        int gi = ibase + ir;
#pragma unroll
        for (int c = 0; c < 4; c++) {
            int jc = tx + 32 * c;
            int idj = sIdJ[jc];
            int gj = jbase + jc;
            if ((offdiag || gi < gj) && idi != idj) {
                unsigned long long v = acc[r][c];
                float lo = __uint_as_float((unsigned)v);
                float hi = __uint_as_float((unsigned)(v >> 32));
                float ed = (lo + hi) * inv64;
                loss += fabsf(ed - sM[(r * 4 + c) * 1024 + tid]);
                cnt += 1.0f;
            }
        }
    }

#pragma unroll
    for (int o = 16; o; o >>= 1) {
        loss += __shfl_xor_sync(0xffffffffu, loss, o);
        cnt  += __shfl_xor_sync(0xffffffffu, cnt, o);
    }
    __syncthreads();  // smem reuse for reduction
    float* red = (float*)smem_raw;
    int lane = tid & 31, w = tid >> 5;
    if (lane == 0) { red[w] = loss; red[32 + w] = cnt; }
    __syncthreads();
    if (tid == 0) {
        float L = 0.0f, C = 0.0f;
#pragma unroll
        for (int i = 0; i < 32; i++) { L += red[i]; C += red[32 + i]; }
        g_psum[blockIdx.x] = L;   // plain overwrite (deterministic)
        g_pcnt[blockIdx.x] = C;
    }
}

__global__ void k_final(float* out) {
    float L = 0.0f, C = 0.0f;
    int lane = threadIdx.x;                 // 1 warp
    for (int i = lane; i < NTILES; i += 32) { L += g_psum[i]; C += g_pcnt[i]; }
#pragma unroll
    for (int o = 16; o; o >>= 1) {
        L += __shfl_xor_sync(0xffffffffu, L, o);
        C += __shfl_xor_sync(0xffffffffu, C, o);
    }
    if (lane == 0) out[0] = L / C;
}

// ---------------------------------------------------------------------------
extern "C" void kernel_launch(void* const* d_in, const int* in_sizes, int n_in,
                              void* d_out, int out_size) {
    const int*   ids  = (const int*)d_in[0];
    const float* emb  = (const float*)d_in[1];
    const float* tree = (const float*)d_in[2];
    const float* mapd = (const float*)d_in[3];
    float* out = (float*)d_out;

    // smem: tiles 67584 + ids 1024 + metric 65536 = 134144 B
    const int SMEM_BYTES = 2 * TB * PADK * 8 + 2 * TB * 4 + 16 * 1024 * 4;
    cudaFuncSetAttribute(k_main, cudaFuncAttributeMaxDynamicSharedMemorySize,
                         SMEM_BYTES);

    k_max<<<MAXB, 1024>>>((const float4*)mapd);
    k_table<<<(Vv * Vv / 4) / 1024, 1024>>>((const float4*)tree,
                                            (const float4*)mapd);
    k_main<<<NTILES, 1024, SMEM_BYTES>>>(ids, (const float2*)emb);
    k_final<<<1, 32>>>(out);
}